// round 7
// baseline (speedup 1.0000x reference)
#include <cuda_runtime.h>

#define NPOS 900
#define BATCH 4
#define VV 16
#define HH 8
#define DQ 256
#define MQUAD 225   // 900 / 4 m-values per thread
#define RPB 2       // rows per block

__device__ __forceinline__ unsigned long long pk2(float lo, float hi) {
    unsigned long long r;
    asm("mov.b64 %0,{%1,%2};" : "=l"(r) : "f"(lo), "f"(hi));
    return r;
}
__device__ __forceinline__ void upk2(unsigned long long v, float& lo, float& hi) {
    asm("mov.b64 {%0,%1},%2;" : "=f"(lo), "=f"(hi) : "l"(v));
}
__device__ __forceinline__ unsigned long long ffma2(unsigned long long a,
                                                    unsigned long long b,
                                                    unsigned long long c) {
    unsigned long long r;
    asm("fma.rn.f32x2 %0,%1,%2,%3;" : "=l"(r) : "l"(a), "l"(b), "l"(c));
    return r;
}

// One block per (b, n-pair). Two rows share the centers tile and one set of
// barriers; phase D handles the rows sequentially to cap register pressure.
__global__ __launch_bounds__(256, 4)
void hough_fused_kernel(
    const float* __restrict__ q,       // (B,N,256)
    const float* __restrict__ ref,     // (B,N,4)
    const float* __restrict__ vote_w,  // (32,256)
    const float* __restrict__ vote_b,  // (32)
    const float* __restrict__ proj_w,  // (8,16)
    const float* __restrict__ proj_b,  // (8)
    float* __restrict__ out)           // (B,8,N,N)
{
    __shared__ float  s_q[RPB][DQ];
    __shared__ float4 s_vc[RPB][VV];             // {vfx, vfy, |vf|^2, -1/(2 sigma^2)}
    __shared__ float2 s_cen[NPOS];
    __shared__ unsigned long long s_ws[HH][8];   // (w_sin, w_sin) duplicated
    __shared__ unsigned long long s_wc[HH][8];   // (w_cos, w_cos) duplicated
    __shared__ float  s_pb[HH];
    __shared__ float  s_red[RPB][8];
    __shared__ float  s_vp[RPB][32];

    const int blk  = blockIdx.x;
    const int b    = blk / (NPOS / RPB);
    const int n0   = (blk % (NPOS / RPB)) * RPB;
    const int tid  = threadIdx.x;
    const int lane = tid & 31;
    const int w    = tid >> 5;

    // ---------------- phase A: loads ----------------
    s_q[0][tid] = q[(b * NPOS + n0) * DQ + tid];
    s_q[1][tid] = q[(b * NPOS + n0 + 1) * DQ + tid];
    for (int m = tid; m < NPOS; m += 256) {
        const float2* rp = reinterpret_cast<const float2*>(ref + (b * NPOS + m) * 4);
        s_cen[m] = rp[0];
    }
    if (tid < 64) {
        int h = tid >> 3, k = tid & 7;
        float wx = proj_w[h * 16 + 2 * k];
        float wy = proj_w[h * 16 + 2 * k + 1];
        s_ws[h][k] = pk2(wx, wx);
        s_wc[h][k] = pk2(wy, wy);
    }
    if (tid < HH) s_pb[tid] = proj_b[tid];
    __syncthreads();

    // ---------------- phase B: votes, 8 dots per warp (2 rows x 32) ----------------
    {
        const int row = w >> 2;          // warps 0-3 -> row0, 4-7 -> row1
        const int j0  = (w & 3) * 8;
        float a[8];
        #pragma unroll
        for (int j = 0; j < 8; ++j) a[j] = 0.f;
        #pragma unroll
        for (int t = 0; t < 8; ++t) {
            int d = lane + t * 32;
            float qv = s_q[row][d];
            #pragma unroll
            for (int j = 0; j < 8; ++j)
                a[j] = fmaf(qv, vote_w[(j0 + j) * DQ + d], a[j]);
        }
        #pragma unroll
        for (int o = 16; o > 0; o >>= 1) {
            #pragma unroll
            for (int j = 0; j < 8; ++j)
                a[j] += __shfl_xor_sync(0xffffffffu, a[j], o);
        }
        if (lane == 0) {
            #pragma unroll
            for (int j = 0; j < 8; ++j)
                s_vp[row][j0 + j] = a[j] + vote_b[j0 + j];
        }
    }
    __syncthreads();

    if (tid < RPB * VV) {
        int row = tid >> 4, v = tid & 15;
        int n = n0 + row;
        float rx = ref[(b * NPOS + n) * 4 + 0];
        float ry = ref[(b * NPOS + n) * 4 + 1];
        float vfx = rx + s_vp[row][2 * v + 0];
        float vfy = ry + s_vp[row][2 * v + 1];
        // reference quirk: sigma_flat = tile(sigma,(1,V,1)) -> index (n*V+v) mod N
        int idx = (n * VV + v) % NPOS;
        float r2 = ref[(b * NPOS + idx) * 4 + 2];
        float r3 = ref[(b * NPOS + idx) * 4 + 3];
        float sigma = (r2 + r3) * 0.25f;
        float den = fmaxf(2.0f * sigma * sigma, 1e-38f);
        float ninv = -1.0f / den;
        s_vc[row][v] = make_float4(vfx, vfy, fmaf(vfx, vfx, vfy * vfy), ninv);
    }
    __syncthreads();

    // ---------------- phase C: 4 m x 2 rows per thread ----------------
    float a00 = 0.f, a01 = 0.f, a02 = 0.f, a03 = 0.f;   // row 0
    float a10 = 0.f, a11 = 0.f, a12 = 0.f, a13 = 0.f;   // row 1
    if (tid < MQUAD) {
        const float4* cp = reinterpret_cast<const float4*>(&s_cen[4 * tid]);
        float4 cA = cp[0], cB = cp[1];
        float2 c0 = make_float2(cA.x, cA.y), c1 = make_float2(cA.z, cA.w);
        float2 c2 = make_float2(cB.x, cB.y), c3 = make_float2(cB.z, cB.w);
        float q0 = fmaf(c0.x, c0.x, c0.y * c0.y);
        float q1 = fmaf(c1.x, c1.x, c1.y * c1.y);
        float q2 = fmaf(c2.x, c2.x, c2.y * c2.y);
        float q3 = fmaf(c3.x, c3.x, c3.y * c3.y);
        #pragma unroll
        for (int v = 0; v < VV; ++v) {
            float4 p0 = s_vc[0][v];
            float4 p1 = s_vc[1][v];
            float d00 = fmaf(-2.0f, fmaf(p0.x, c0.x, p0.y * c0.y), p0.z + q0);
            float d01 = fmaf(-2.0f, fmaf(p0.x, c1.x, p0.y * c1.y), p0.z + q1);
            float d02 = fmaf(-2.0f, fmaf(p0.x, c2.x, p0.y * c2.y), p0.z + q2);
            float d03 = fmaf(-2.0f, fmaf(p0.x, c3.x, p0.y * c3.y), p0.z + q3);
            float d10 = fmaf(-2.0f, fmaf(p1.x, c0.x, p1.y * c0.y), p1.z + q0);
            float d11 = fmaf(-2.0f, fmaf(p1.x, c1.x, p1.y * c1.y), p1.z + q1);
            float d12 = fmaf(-2.0f, fmaf(p1.x, c2.x, p1.y * c2.y), p1.z + q2);
            float d13 = fmaf(-2.0f, fmaf(p1.x, c3.x, p1.y * c3.y), p1.z + q3);
            a00 += __expf(p0.w * fmaxf(d00, 0.0f));
            a01 += __expf(p0.w * fmaxf(d01, 0.0f));
            a02 += __expf(p0.w * fmaxf(d02, 0.0f));
            a03 += __expf(p0.w * fmaxf(d03, 0.0f));
            a10 += __expf(p1.w * fmaxf(d10, 0.0f));
            a11 += __expf(p1.w * fmaxf(d11, 0.0f));
            a12 += __expf(p1.w * fmaxf(d12, 0.0f));
            a13 += __expf(p1.w * fmaxf(d13, 0.0f));
        }
    }
    float rs0 = (a00 + a01) + (a02 + a03);
    float rs1 = (a10 + a11) + (a12 + a13);
    #pragma unroll
    for (int o = 16; o > 0; o >>= 1) {
        rs0 += __shfl_xor_sync(0xffffffffu, rs0, o);
        rs1 += __shfl_xor_sync(0xffffffffu, rs1, o);
    }
    if (lane == 0) { s_red[0][w] = rs0; s_red[1][w] = rs1; }
    __syncthreads();

    float t0 = s_red[0][0], t1 = s_red[1][0];
    #pragma unroll
    for (int i = 1; i < 8; ++i) { t0 += s_red[0][i]; t1 += s_red[1][i]; }
    const float invd[RPB] = { 1.0f / fmaxf(t0, 1e-12f), 1.0f / fmaxf(t1, 1e-12f) };

    if (tid >= MQUAD) return;

    const float arow[RPB][4] = { {a00, a01, a02, a03}, {a10, a11, a12, a13} };

    // omega_k = 100 / 10000^(k/8) = 100 * 10^(-k/2)
    const float omega[8] = {100.0f, 31.622776601683793f, 10.0f, 3.1622776601683795f,
                            1.0f, 0.31622776601683794f, 0.1f, 0.031622776601683794f};

    // ---------------- phase D+E per row (sequential to cap registers) ----------------
    #pragma unroll
    for (int r = 0; r < RPB; ++r) {
        const float x0 = 1.0f - arow[r][0] * invd[r];
        const float x1 = 1.0f - arow[r][1] * invd[r];
        const float x2 = 1.0f - arow[r][2] * invd[r];
        const float x3 = 1.0f - arow[r][3] * invd[r];

        unsigned long long acc[HH][2];
        #pragma unroll
        for (int h = 0; h < HH; ++h) {
            float pb = s_pb[h];
            acc[h][0] = pk2(pb, pb);
            acc[h][1] = pk2(pb, pb);
        }
        #pragma unroll
        for (int k = 0; k < 8; ++k) {
            float sA, cA, sB, cB, sC, cC, sD, cD;
            __sincosf(x0 * omega[k], &sA, &cA);
            __sincosf(x1 * omega[k], &sB, &cB);
            __sincosf(x2 * omega[k], &sC, &cC);
            __sincosf(x3 * omega[k], &sD, &cD);
            unsigned long long s01 = pk2(sA, sB), s23 = pk2(sC, sD);
            unsigned long long c01 = pk2(cA, cB), c23 = pk2(cC, cD);
            #pragma unroll
            for (int h = 0; h < HH; ++h) {
                unsigned long long ws = s_ws[h][k];
                unsigned long long wc = s_wc[h][k];
                acc[h][0] = ffma2(ws, s01, ffma2(wc, c01, acc[h][0]));
                acc[h][1] = ffma2(ws, s23, ffma2(wc, c23, acc[h][1]));
            }
        }
        #pragma unroll
        for (int h = 0; h < HH; ++h) {
            float o0, o1, o2, o3;
            upk2(acc[h][0], o0, o1);
            upk2(acc[h][1], o2, o3);
            float4 vv = make_float4(fmaxf(o0, 0.0f), fmaxf(o1, 0.0f),
                                    fmaxf(o2, 0.0f), fmaxf(o3, 0.0f));
            float4* dst = reinterpret_cast<float4*>(
                out + ((size_t)((b * HH + h) * NPOS) + n0 + r) * NPOS);
            dst[tid] = vv;
        }
    }
}

extern "C" void kernel_launch(void* const* d_in, const int* in_sizes, int n_in,
                              void* d_out, int out_size) {
    const float* q      = (const float*)d_in[0];
    const float* ref    = (const float*)d_in[1];
    const float* vote_w = (const float*)d_in[3];
    const float* vote_b = (const float*)d_in[4];
    const float* proj_w = (const float*)d_in[5];
    const float* proj_b = (const float*)d_in[6];
    float* out = (float*)d_out;

    (void)in_sizes; (void)n_in; (void)out_size;

    dim3 grid(BATCH * NPOS / RPB);
    dim3 block(256);
    hough_fused_kernel<<<grid, block>>>(q, ref, vote_w, vote_b, proj_w, proj_b, out);
}

// round 8
// speedup vs baseline: 2.7204x; 2.7204x over previous
#include <cuda_runtime.h>

#define NPOS 900
#define BATCH 4
#define VV 16
#define HH 8
#define DQ 256
#define MQUAD 225   // 900 / 4 m-values per thread
#define RPB 2       // rows per block

__device__ __forceinline__ unsigned long long pk2(float lo, float hi) {
    unsigned long long r;
    asm("mov.b64 %0,{%1,%2};" : "=l"(r) : "f"(lo), "f"(hi));
    return r;
}
__device__ __forceinline__ void upk2(unsigned long long v, float& lo, float& hi) {
    asm("mov.b64 {%0,%1},%2;" : "=f"(lo), "=f"(hi) : "l"(v));
}
__device__ __forceinline__ unsigned long long ffma2(unsigned long long a,
                                                    unsigned long long b,
                                                    unsigned long long c) {
    unsigned long long r;
    asm("fma.rn.f32x2 %0,%1,%2,%3;" : "=l"(r) : "l"(a), "l"(b), "l"(c));
    return r;
}

// One block per (b, n-pair). The two rows share phase A/B (centers tile,
// weights, votes GEMM) but phases C/D run fully sequentially per row so the
// live register set never exceeds the R5 (single-row) profile -> no spills
// under the 64-reg / 4-blocks-per-SM cap.
__global__ __launch_bounds__(256, 4)
void hough_fused_kernel(
    const float* __restrict__ q,       // (B,N,256)
    const float* __restrict__ ref,     // (B,N,4)
    const float* __restrict__ vote_w,  // (32,256)
    const float* __restrict__ vote_b,  // (32)
    const float* __restrict__ proj_w,  // (8,16)
    const float* __restrict__ proj_b,  // (8)
    float* __restrict__ out)           // (B,8,N,N)
{
    __shared__ float  s_q[RPB][DQ];
    __shared__ float4 s_vc[RPB][VV];             // {vfx, vfy, |vf|^2, -1/(2 sigma^2)}
    __shared__ float2 s_cen[NPOS];
    __shared__ unsigned long long s_ws[HH][8];   // (w_sin, w_sin) duplicated
    __shared__ unsigned long long s_wc[HH][8];   // (w_cos, w_cos) duplicated
    __shared__ float  s_pb[HH];
    __shared__ float  s_red[RPB][8];
    __shared__ float  s_vp[RPB][32];

    const int blk  = blockIdx.x;
    const int b    = blk / (NPOS / RPB);
    const int n0   = (blk % (NPOS / RPB)) * RPB;
    const int tid  = threadIdx.x;
    const int lane = tid & 31;
    const int w    = tid >> 5;

    // ---------------- phase A: loads ----------------
    s_q[0][tid] = q[(b * NPOS + n0) * DQ + tid];
    s_q[1][tid] = q[(b * NPOS + n0 + 1) * DQ + tid];
    for (int m = tid; m < NPOS; m += 256) {
        const float2* rp = reinterpret_cast<const float2*>(ref + (b * NPOS + m) * 4);
        s_cen[m] = rp[0];
    }
    if (tid < 64) {
        int h = tid >> 3, k = tid & 7;
        float wx = proj_w[h * 16 + 2 * k];
        float wy = proj_w[h * 16 + 2 * k + 1];
        s_ws[h][k] = pk2(wx, wx);
        s_wc[h][k] = pk2(wy, wy);
    }
    if (tid < HH) s_pb[tid] = proj_b[tid];
    __syncthreads();

    // ---------------- phase B: votes, 8 dots per warp (2 rows x 32) ----------------
    {
        const int row = w >> 2;          // warps 0-3 -> row0, 4-7 -> row1
        const int j0  = (w & 3) * 8;
        float a[8];
        #pragma unroll
        for (int j = 0; j < 8; ++j) a[j] = 0.f;
        #pragma unroll
        for (int t = 0; t < 8; ++t) {
            int d = lane + t * 32;
            float qv = s_q[row][d];
            #pragma unroll
            for (int j = 0; j < 8; ++j)
                a[j] = fmaf(qv, vote_w[(j0 + j) * DQ + d], a[j]);
        }
        #pragma unroll
        for (int o = 16; o > 0; o >>= 1) {
            #pragma unroll
            for (int j = 0; j < 8; ++j)
                a[j] += __shfl_xor_sync(0xffffffffu, a[j], o);
        }
        if (lane == 0) {
            #pragma unroll
            for (int j = 0; j < 8; ++j)
                s_vp[row][j0 + j] = a[j] + vote_b[j0 + j];
        }
    }
    __syncthreads();

    if (tid < RPB * VV) {
        int row = tid >> 4, v = tid & 15;
        int n = n0 + row;
        float rx = ref[(b * NPOS + n) * 4 + 0];
        float ry = ref[(b * NPOS + n) * 4 + 1];
        float vfx = rx + s_vp[row][2 * v + 0];
        float vfy = ry + s_vp[row][2 * v + 1];
        // reference quirk: sigma_flat = tile(sigma,(1,V,1)) -> index (n*V+v) mod N
        int idx = (n * VV + v) % NPOS;
        float r2 = ref[(b * NPOS + idx) * 4 + 2];
        float r3 = ref[(b * NPOS + idx) * 4 + 3];
        float sigma = (r2 + r3) * 0.25f;
        float den = fmaxf(2.0f * sigma * sigma, 1e-38f);
        float ninv = -1.0f / den;
        s_vc[row][v] = make_float4(vfx, vfy, fmaf(vfx, vfx, vfy * vfy), ninv);
    }
    __syncthreads();

    // omega_k = 100 / 10000^(k/8) = 100 * 10^(-k/2)
    const float omega[8] = {100.0f, 31.622776601683793f, 10.0f, 3.1622776601683795f,
                            1.0f, 0.31622776601683794f, 0.1f, 0.031622776601683794f};

    // ---------------- rows processed fully sequentially ----------------
    #pragma unroll
    for (int r = 0; r < RPB; ++r) {
        // ---- phase C: 4 imap values per thread + row sum ----
        float a0 = 0.f, a1 = 0.f, a2 = 0.f, a3 = 0.f;
        if (tid < MQUAD) {
            const float4* cp = reinterpret_cast<const float4*>(&s_cen[4 * tid]);
            float4 cA = cp[0], cB = cp[1];
            float2 c0 = make_float2(cA.x, cA.y), c1 = make_float2(cA.z, cA.w);
            float2 c2 = make_float2(cB.x, cB.y), c3 = make_float2(cB.z, cB.w);
            float q0 = fmaf(c0.x, c0.x, c0.y * c0.y);
            float q1 = fmaf(c1.x, c1.x, c1.y * c1.y);
            float q2 = fmaf(c2.x, c2.x, c2.y * c2.y);
            float q3 = fmaf(c3.x, c3.x, c3.y * c3.y);
            #pragma unroll
            for (int v = 0; v < VV; ++v) {
                float4 p = s_vc[r][v];
                float d0 = fmaf(-2.0f, fmaf(p.x, c0.x, p.y * c0.y), p.z + q0);
                float d1 = fmaf(-2.0f, fmaf(p.x, c1.x, p.y * c1.y), p.z + q1);
                float d2 = fmaf(-2.0f, fmaf(p.x, c2.x, p.y * c2.y), p.z + q2);
                float d3 = fmaf(-2.0f, fmaf(p.x, c3.x, p.y * c3.y), p.z + q3);
                a0 += __expf(p.w * fmaxf(d0, 0.0f));
                a1 += __expf(p.w * fmaxf(d1, 0.0f));
                a2 += __expf(p.w * fmaxf(d2, 0.0f));
                a3 += __expf(p.w * fmaxf(d3, 0.0f));
            }
        }
        float rowsum = (a0 + a1) + (a2 + a3);
        #pragma unroll
        for (int o = 16; o > 0; o >>= 1)
            rowsum += __shfl_xor_sync(0xffffffffu, rowsum, o);
        if (lane == 0) s_red[r][w] = rowsum;
        __syncthreads();

        float total = s_red[r][0];
        #pragma unroll
        for (int i = 1; i < 8; ++i) total += s_red[r][i];
        const float invd = 1.0f / fmaxf(total, 1e-12f);

        if (tid < MQUAD) {
            const float x0 = 1.0f - a0 * invd;
            const float x1 = 1.0f - a1 * invd;
            const float x2 = 1.0f - a2 * invd;
            const float x3 = 1.0f - a3 * invd;

            // ---- phase D: pos-embed + projection for 4 m ----
            unsigned long long acc[HH][2];
            #pragma unroll
            for (int h = 0; h < HH; ++h) {
                float pb = s_pb[h];
                acc[h][0] = pk2(pb, pb);
                acc[h][1] = pk2(pb, pb);
            }
            #pragma unroll
            for (int k = 0; k < 8; ++k) {
                float sA, cA, sB, cB, sC, cC, sD, cD;
                __sincosf(x0 * omega[k], &sA, &cA);
                __sincosf(x1 * omega[k], &sB, &cB);
                __sincosf(x2 * omega[k], &sC, &cC);
                __sincosf(x3 * omega[k], &sD, &cD);
                unsigned long long s01 = pk2(sA, sB), s23 = pk2(sC, sD);
                unsigned long long c01 = pk2(cA, cB), c23 = pk2(cC, cD);
                #pragma unroll
                for (int h = 0; h < HH; ++h) {
                    unsigned long long ws = s_ws[h][k];
                    unsigned long long wc = s_wc[h][k];
                    acc[h][0] = ffma2(ws, s01, ffma2(wc, c01, acc[h][0]));
                    acc[h][1] = ffma2(ws, s23, ffma2(wc, c23, acc[h][1]));
                }
            }

            // ---- phase E: direct STG.128 per head ----
            #pragma unroll
            for (int h = 0; h < HH; ++h) {
                float o0, o1, o2, o3;
                upk2(acc[h][0], o0, o1);
                upk2(acc[h][1], o2, o3);
                float4 vv = make_float4(fmaxf(o0, 0.0f), fmaxf(o1, 0.0f),
                                        fmaxf(o2, 0.0f), fmaxf(o3, 0.0f));
                float4* dst = reinterpret_cast<float4*>(
                    out + ((size_t)((b * HH + h) * NPOS) + n0 + r) * NPOS);
                dst[tid] = vv;
            }
        }
    }
}

extern "C" void kernel_launch(void* const* d_in, const int* in_sizes, int n_in,
                              void* d_out, int out_size) {
    const float* q      = (const float*)d_in[0];
    const float* ref    = (const float*)d_in[1];
    const float* vote_w = (const float*)d_in[3];
    const float* vote_b = (const float*)d_in[4];
    const float* proj_w = (const float*)d_in[5];
    const float* proj_b = (const float*)d_in[6];
    float* out = (float*)d_out;

    (void)in_sizes; (void)n_in; (void)out_size;

    dim3 grid(BATCH * NPOS / RPB);
    dim3 block(256);
    hough_fused_kernel<<<grid, block>>>(q, ref, vote_w, vote_b, proj_w, proj_b, out);
}

// round 11
// speedup vs baseline: 4.1027x; 1.5082x over previous
#include <cuda_runtime.h>

#define NPOS 900
#define BATCH 4
#define VV 16
#define HH 8
#define DQ 256
#define MQUAD 225   // 900 / 4 m-values per thread

__device__ __forceinline__ unsigned long long pk2(float lo, float hi) {
    unsigned long long r;
    asm("mov.b64 %0,{%1,%2};" : "=l"(r) : "f"(lo), "f"(hi));
    return r;
}
__device__ __forceinline__ void upk2(unsigned long long v, float& lo, float& hi) {
    asm("mov.b64 {%0,%1},%2;" : "=f"(lo), "=f"(hi) : "l"(v));
}
__device__ __forceinline__ unsigned long long ffma2(unsigned long long a,
                                                    unsigned long long b,
                                                    unsigned long long c) {
    unsigned long long r;
    asm("fma.rn.f32x2 %0,%1,%2,%3;" : "=l"(r) : "l"(a), "l"(b), "l"(c));
    return r;
}
__device__ __forceinline__ void stcs128(float4* p, float4 v) {
    asm volatile("st.global.cs.v4.f32 [%0],{%1,%2,%3,%4};"
                 :: "l"(p), "f"(v.x), "f"(v.y), "f"(v.z), "f"(v.w) : "memory");
}

// R5 structure (1 row / block, 4 m per thread, zero spill) + streaming output
// stores so the 104MB write stream doesn't evict vote_w/centers/q from L2.
__global__ __launch_bounds__(256, 4)
void hough_fused_kernel(
    const float* __restrict__ q,       // (B,N,256)
    const float* __restrict__ ref,     // (B,N,4)
    const float* __restrict__ vote_w,  // (32,256)
    const float* __restrict__ vote_b,  // (32)
    const float* __restrict__ proj_w,  // (8,16)
    const float* __restrict__ proj_b,  // (8)
    float* __restrict__ out)           // (B,8,N,N)
{
    __shared__ float  s_q[DQ];
    __shared__ float4 s_vc[VV];                  // {vfx, vfy, |vf|^2, -1/(2 sigma^2)}
    __shared__ float2 s_cen[NPOS];
    __shared__ unsigned long long s_ws[HH][8];   // (w_sin, w_sin) duplicated
    __shared__ unsigned long long s_wc[HH][8];   // (w_cos, w_cos) duplicated
    __shared__ float  s_pb[HH];
    __shared__ float  s_red[8];
    __shared__ float  s_vp[32];

    const int blk  = blockIdx.x;
    const int b    = blk / NPOS;
    const int n    = blk % NPOS;
    const int tid  = threadIdx.x;
    const int lane = tid & 31;
    const int w    = tid >> 5;

    // ---------------- phase A: loads ----------------
    s_q[tid] = __ldg(&q[(b * NPOS + n) * DQ + tid]);
    for (int m = tid; m < NPOS; m += 256) {
        const float2* rp = reinterpret_cast<const float2*>(ref + (b * NPOS + m) * 4);
        s_cen[m] = __ldg(rp);
    }
    if (tid < 64) {
        int h = tid >> 3, k = tid & 7;
        float wx = __ldg(&proj_w[h * 16 + 2 * k]);
        float wy = __ldg(&proj_w[h * 16 + 2 * k + 1]);
        s_ws[h][k] = pk2(wx, wx);
        s_wc[h][k] = pk2(wy, wy);
    }
    if (tid < HH) s_pb[tid] = __ldg(&proj_b[tid]);
    __syncthreads();

    // ---------------- phase B: votes (32 x 256 dot) ----------------
    {
        const int j0 = w * 4;
        float a0 = 0.f, a1 = 0.f, a2 = 0.f, a3 = 0.f;
        #pragma unroll
        for (int t = 0; t < 8; ++t) {
            int d = lane + t * 32;
            float qv = s_q[d];
            a0 = fmaf(qv, __ldg(&vote_w[(j0 + 0) * DQ + d]), a0);
            a1 = fmaf(qv, __ldg(&vote_w[(j0 + 1) * DQ + d]), a1);
            a2 = fmaf(qv, __ldg(&vote_w[(j0 + 2) * DQ + d]), a2);
            a3 = fmaf(qv, __ldg(&vote_w[(j0 + 3) * DQ + d]), a3);
        }
        #pragma unroll
        for (int o = 16; o > 0; o >>= 1) {
            a0 += __shfl_xor_sync(0xffffffffu, a0, o);
            a1 += __shfl_xor_sync(0xffffffffu, a1, o);
            a2 += __shfl_xor_sync(0xffffffffu, a2, o);
            a3 += __shfl_xor_sync(0xffffffffu, a3, o);
        }
        if (lane == 0) {
            s_vp[j0 + 0] = a0 + __ldg(&vote_b[j0 + 0]);
            s_vp[j0 + 1] = a1 + __ldg(&vote_b[j0 + 1]);
            s_vp[j0 + 2] = a2 + __ldg(&vote_b[j0 + 2]);
            s_vp[j0 + 3] = a3 + __ldg(&vote_b[j0 + 3]);
        }
    }
    __syncthreads();

    if (tid < VV) {
        int v = tid;
        float rx = __ldg(&ref[(b * NPOS + n) * 4 + 0]);
        float ry = __ldg(&ref[(b * NPOS + n) * 4 + 1]);
        float vfx = rx + s_vp[2 * v + 0];
        float vfy = ry + s_vp[2 * v + 1];
        // reference quirk: sigma_flat = tile(sigma,(1,V,1)) -> index (n*V+v) mod N
        int idx = (n * VV + v) % NPOS;
        float r2 = __ldg(&ref[(b * NPOS + idx) * 4 + 2]);
        float r3 = __ldg(&ref[(b * NPOS + idx) * 4 + 3]);
        float sigma = (r2 + r3) * 0.25f;
        float den = fmaxf(2.0f * sigma * sigma, 1e-38f);
        float ninv = -1.0f / den;
        s_vc[v] = make_float4(vfx, vfy, fmaf(vfx, vfx, vfy * vfy), ninv);
    }
    __syncthreads();

    // ---------------- phase C: 4 imap values per thread + row sum ----------------
    float a0 = 0.f, a1 = 0.f, a2 = 0.f, a3 = 0.f;
    if (tid < MQUAD) {
        const float4* cp = reinterpret_cast<const float4*>(&s_cen[4 * tid]);
        float4 cA = cp[0], cB = cp[1];
        float2 c0 = make_float2(cA.x, cA.y), c1 = make_float2(cA.z, cA.w);
        float2 c2 = make_float2(cB.x, cB.y), c3 = make_float2(cB.z, cB.w);
        float q0 = fmaf(c0.x, c0.x, c0.y * c0.y);
        float q1 = fmaf(c1.x, c1.x, c1.y * c1.y);
        float q2 = fmaf(c2.x, c2.x, c2.y * c2.y);
        float q3 = fmaf(c3.x, c3.x, c3.y * c3.y);
        #pragma unroll
        for (int v = 0; v < VV; ++v) {
            float4 p = s_vc[v];
            float d0 = fmaf(-2.0f, fmaf(p.x, c0.x, p.y * c0.y), p.z + q0);
            float d1 = fmaf(-2.0f, fmaf(p.x, c1.x, p.y * c1.y), p.z + q1);
            float d2 = fmaf(-2.0f, fmaf(p.x, c2.x, p.y * c2.y), p.z + q2);
            float d3 = fmaf(-2.0f, fmaf(p.x, c3.x, p.y * c3.y), p.z + q3);
            a0 += __expf(p.w * fmaxf(d0, 0.0f));
            a1 += __expf(p.w * fmaxf(d1, 0.0f));
            a2 += __expf(p.w * fmaxf(d2, 0.0f));
            a3 += __expf(p.w * fmaxf(d3, 0.0f));
        }
    }
    float rowsum = (a0 + a1) + (a2 + a3);
    #pragma unroll
    for (int o = 16; o > 0; o >>= 1)
        rowsum += __shfl_xor_sync(0xffffffffu, rowsum, o);
    if (lane == 0) s_red[w] = rowsum;
    __syncthreads();

    float total = s_red[0];
    #pragma unroll
    for (int i = 1; i < 8; ++i) total += s_red[i];
    const float invd = 1.0f / fmaxf(total, 1e-12f);

    if (tid >= MQUAD) return;

    const float x0 = 1.0f - a0 * invd;
    const float x1 = 1.0f - a1 * invd;
    const float x2 = 1.0f - a2 * invd;
    const float x3 = 1.0f - a3 * invd;

    // omega_k = 100 / 10000^(k/8) = 100 * 10^(-k/2)
    const float omega[8] = {100.0f, 31.622776601683793f, 10.0f, 3.1622776601683795f,
                            1.0f, 0.31622776601683794f, 0.1f, 0.031622776601683794f};

    // ---------------- phase D: pos-embed + projection for 4 m at once ----------------
    unsigned long long acc[HH][2];
    #pragma unroll
    for (int h = 0; h < HH; ++h) {
        float pb = s_pb[h];
        acc[h][0] = pk2(pb, pb);
        acc[h][1] = pk2(pb, pb);
    }
    #pragma unroll
    for (int k = 0; k < 8; ++k) {
        float sA, cA, sB, cB, sC, cC, sD, cD;
        __sincosf(x0 * omega[k], &sA, &cA);
        __sincosf(x1 * omega[k], &sB, &cB);
        __sincosf(x2 * omega[k], &sC, &cC);
        __sincosf(x3 * omega[k], &sD, &cD);
        unsigned long long s01 = pk2(sA, sB), s23 = pk2(sC, sD);
        unsigned long long c01 = pk2(cA, cB), c23 = pk2(cC, cD);
        #pragma unroll
        for (int h = 0; h < HH; ++h) {
            unsigned long long ws = s_ws[h][k];
            unsigned long long wc = s_wc[h][k];
            acc[h][0] = ffma2(ws, s01, ffma2(wc, c01, acc[h][0]));
            acc[h][1] = ffma2(ws, s23, ffma2(wc, c23, acc[h][1]));
        }
    }

    // ---------------- phase E: streaming STG.128 per head ----------------
    #pragma unroll
    for (int h = 0; h < HH; ++h) {
        float o0, o1, o2, o3;
        upk2(acc[h][0], o0, o1);
        upk2(acc[h][1], o2, o3);
        float4 vv = make_float4(fmaxf(o0, 0.0f), fmaxf(o1, 0.0f),
                                fmaxf(o2, 0.0f), fmaxf(o3, 0.0f));
        float4* dst = reinterpret_cast<float4*>(
            out + ((size_t)((b * HH + h) * NPOS) + n) * NPOS);
        stcs128(dst + tid, vv);
    }
}

extern "C" void kernel_launch(void* const* d_in, const int* in_sizes, int n_in,
                              void* d_out, int out_size) {
    const float* q      = (const float*)d_in[0];
    const float* ref    = (const float*)d_in[1];
    const float* vote_w = (const float*)d_in[3];
    const float* vote_b = (const float*)d_in[4];
    const float* proj_w = (const float*)d_in[5];
    const float* proj_b = (const float*)d_in[6];
    float* out = (float*)d_out;

    (void)in_sizes; (void)n_in; (void)out_size;

    dim3 grid(BATCH * NPOS);
    dim3 block(256);
    hough_fused_kernel<<<grid, block>>>(q, ref, vote_w, vote_b, proj_w, proj_b, out);
}